// round 3
// baseline (speedup 1.0000x reference)
#include <cuda_runtime.h>
#include <math.h>

#define NN 50000
#define EE 800000
#define HH 128
#define SS 5000
#define GG 64

// Scratch (device globals: no allocation allowed)
__device__ float g_h   [NN*HH];
__device__ float g_h2  [NN*HH];
__device__ float g_aggr[NN*HH];
__device__ float g_pool[(SS+GG)*HH];
__device__ int   g_rowptr[NN+1];
__device__ int   g_cur[NN];
__device__ int   g_csr[EE];
__device__ int   g_bsum[64];

// ---------------------------------------------------------------------------
// packed f32x2 helpers
__device__ __forceinline__ unsigned long long pack2(float lo, float hi) {
    unsigned long long r;
    asm("mov.b64 %0, {%1, %2};" : "=l"(r) : "f"(lo), "f"(hi));
    return r;
}
__device__ __forceinline__ unsigned long long fma2(unsigned long long a,
                                                   unsigned long long b,
                                                   unsigned long long c) {
    unsigned long long d;
    asm("fma.rn.f32x2 %0, %1, %2, %3;" : "=l"(d) : "l"(a), "l"(b), "l"(c));
    return d;
}
__device__ __forceinline__ float2 unpack2(unsigned long long v) {
    float2 f;
    asm("mov.b64 {%0, %1}, %2;" : "=f"(f.x), "=f"(f.y) : "l"(v));
    return f;
}

// ---------------------------------------------------------------------------
// Combined zero-init: rowptr counters + pooling buffers
__global__ void init_zero(int* __restrict__ rowptr, float4* __restrict__ pool) {
    int i = blockIdx.x * blockDim.x + threadIdx.x;
    if (i < NN + 1) rowptr[i] = 0;
    if (i < (SS + GG) * HH / 4) pool[i] = make_float4(0.f, 0.f, 0.f, 0.f);
}

__global__ void hist_dst(const int* __restrict__ dst) {
    int e = blockIdx.x * blockDim.x + threadIdx.x;
    if (e < EE) atomicAdd(&g_rowptr[dst[e] + 1], 1);
}

// inclusive scan, 1024-wide blocks
__global__ void scan1(int* __restrict__ data, int* __restrict__ bsum, int n) {
    __shared__ int sh[1024];
    int gid = blockIdx.x * 1024 + threadIdx.x;
    int v = (gid < n) ? data[gid] : 0;
    sh[threadIdx.x] = v;
    __syncthreads();
    for (int off = 1; off < 1024; off <<= 1) {
        int t = (threadIdx.x >= off) ? sh[threadIdx.x - off] : 0;
        __syncthreads();
        sh[threadIdx.x] += t;
        __syncthreads();
    }
    if (gid < n) data[gid] = sh[threadIdx.x];
    if (threadIdx.x == 1023) bsum[blockIdx.x] = sh[1023];
}

// add exclusive block-prefix (computed in-kernel) + write cursor array
__global__ void scan_finish(int* __restrict__ data, const int* __restrict__ bsum,
                            int* __restrict__ cur, int n) {
    __shared__ int offs;
    if (threadIdx.x == 0) {
        int s = 0;
        for (int j = 0; j < blockIdx.x; j++) s += bsum[j];
        offs = s;
    }
    __syncthreads();
    int gid = blockIdx.x * 1024 + threadIdx.x;
    if (gid < n) {
        int v = data[gid] + offs;
        data[gid] = v;
        if (gid < NN) cur[gid] = v;  // cur[i] = rowptr[i]
    }
}

__global__ void fill_csr(const int* __restrict__ src, const int* __restrict__ dst) {
    int e = blockIdx.x * blockDim.x + threadIdx.x;
    if (e >= EE) return;
    int d = dst[e];
    int pos = atomicAdd(&g_cur[d], 1);
    g_csr[pos] = src[e];
}

// ---------------------------------------------------------------------------
// conv1 aggregation (F_IN=2) via CSR gather: one thread per node
__global__ void aggr2_csr(const float* __restrict__ x, float* __restrict__ out) {
    int n = blockIdx.x * blockDim.x + threadIdx.x;
    if (n >= NN) return;
    float2 acc = *(const float2*)(x + 2 * n);
    int p = g_rowptr[n], e = g_rowptr[n + 1];
    for (; p < e; ++p) {
        int s = g_csr[p];
        float2 v = *(const float2*)(x + 2 * s);
        acc.x += v.x; acc.y += v.y;
    }
    *(float2*)(out + 2 * n) = acc;
}

// H=128 aggregation via CSR gather: one warp per node, 4 floats per lane.
__global__ void aggr128_csr(const float* __restrict__ h, float* __restrict__ out) {
    unsigned t = blockIdx.x * blockDim.x + threadIdx.x;
    unsigned n = t >> 5;
    if (n >= NN) return;
    int lane = (int)(t & 31);
    const float* hp = h + lane * 4;
    float4 acc = *(const float4*)(hp + (size_t)n * HH);
    int p = g_rowptr[n], e = g_rowptr[n + 1];
    for (; p + 3 < e; p += 4) {
        int s0 = g_csr[p], s1 = g_csr[p + 1], s2 = g_csr[p + 2], s3 = g_csr[p + 3];
        float4 v0 = *(const float4*)(hp + (size_t)s0 * HH);
        float4 v1 = *(const float4*)(hp + (size_t)s1 * HH);
        float4 v2 = *(const float4*)(hp + (size_t)s2 * HH);
        float4 v3 = *(const float4*)(hp + (size_t)s3 * HH);
        acc.x += (v0.x + v1.x) + (v2.x + v3.x);
        acc.y += (v0.y + v1.y) + (v2.y + v3.y);
        acc.z += (v0.z + v1.z) + (v2.z + v3.z);
        acc.w += (v0.w + v1.w) + (v2.w + v3.w);
    }
    for (; p < e; ++p) {
        int s = g_csr[p];
        float4 v = *(const float4*)(hp + (size_t)s * HH);
        acc.x += v.x; acc.y += v.y; acc.z += v.z; acc.w += v.w;
    }
    *(float4*)(out + (size_t)n * HH + lane * 4) = acc;
}

// ---------------------------------------------------------------------------
// conv1 first linear: (N,2) @ (2,128) + b, relu
__global__ void conv1_lin(const float* __restrict__ aggr2, const float* __restrict__ W1a,
                          const float* __restrict__ b1a, float* __restrict__ out) {
    int idx = blockIdx.x * blockDim.x + threadIdx.x;
    if (idx >= NN * HH) return;
    int n = idx >> 7, j = idx & 127;
    float a0 = aggr2[2 * n], a1 = aggr2[2 * n + 1];
    float v = fmaf(a0, W1a[j], fmaf(a1, W1a[HH + j], b1a[j]));
    out[idx] = fmaxf(v, 0.f);
}

// ---------------------------------------------------------------------------
// C[N,128] = relu(A[N,128] @ W[128,128] + bias), packed f32x2 FMA.
// 256 threads, 128x128 tile, thread = 8x8. A pre-duplicated in smem as (a,a)
// pairs (kills pack MOVs, A-reads become warp broadcasts). Double-buffered
// k-chunks, one __syncthreads per chunk.
__global__ void __launch_bounds__(256, 2)
gemm_relu(const float* __restrict__ A, const float* __restrict__ W,
          const float* __restrict__ bias, float* __restrict__ C) {
    __shared__ unsigned long long As2[2][16][128];  // 32KB, (a,a) pairs, k-major
    __shared__ float Ws[2][16][128];                // 16KB, k-major

    const int tid = threadIdx.x;
    const int tm = (tid >> 4) * 8;   // row offset within tile
    const int tn = (tid & 15) * 8;   // col offset
    const int rowBase = blockIdx.x * 128;

    const int lr = tid >> 1;          // 0..127: A row to load
    const int lk = (tid & 1) * 8;     // k offset 0 or 8
    const int wr = tid >> 5;          // 0..7: W row
    const int wc = (tid & 31) * 4;    // W col

    const bool rowOK = (rowBase + lr) < NN;
    const float* Arow = A + (size_t)(rowBase + lr) * HH;

    unsigned long long acc[8][4];
#pragma unroll
    for (int i = 0; i < 8; i++)
#pragma unroll
        for (int j = 0; j < 4; j++) acc[i][j] = 0ull;

    // stage chunk 0
    float4 a0 = make_float4(0.f,0.f,0.f,0.f), a1 = a0, w0, w1;
    if (rowOK) {
        a0 = *(const float4*)(Arow + lk);
        a1 = *(const float4*)(Arow + lk + 4);
    }
    w0 = *(const float4*)(W + (size_t)wr * HH + wc);
    w1 = *(const float4*)(W + (size_t)(wr + 8) * HH + wc);

#pragma unroll 1
    for (int c = 0; c < 8; c++) {
        const int b = c & 1;
        // commit staged regs to smem buffer b
        {
            float av[8] = {a0.x, a0.y, a0.z, a0.w, a1.x, a1.y, a1.z, a1.w};
#pragma unroll
            for (int i = 0; i < 8; i++) As2[b][lk + i][lr] = pack2(av[i], av[i]);
            *(float4*)&Ws[b][wr][wc]     = w0;
            *(float4*)&Ws[b][wr + 8][wc] = w1;
        }
        __syncthreads();
        // prefetch next chunk into regs
        if (c < 7) {
            int k0 = (c + 1) * 16;
            a0 = make_float4(0.f,0.f,0.f,0.f); a1 = a0;
            if (rowOK) {
                a0 = *(const float4*)(Arow + k0 + lk);
                a1 = *(const float4*)(Arow + k0 + lk + 4);
            }
            w0 = *(const float4*)(W + (size_t)(k0 + wr) * HH + wc);
            w1 = *(const float4*)(W + (size_t)(k0 + wr + 8) * HH + wc);
        }
        // compute from buffer b
#pragma unroll
        for (int kk = 0; kk < 16; kk++) {
            ulonglong2 q0 = *(const ulonglong2*)&As2[b][kk][tm];
            ulonglong2 q1 = *(const ulonglong2*)&As2[b][kk][tm + 2];
            ulonglong2 q2 = *(const ulonglong2*)&As2[b][kk][tm + 4];
            ulonglong2 q3 = *(const ulonglong2*)&As2[b][kk][tm + 6];
            ulonglong2 r0 = *(const ulonglong2*)&Ws[b][kk][tn];
            ulonglong2 r1 = *(const ulonglong2*)&Ws[b][kk][tn + 4];
            unsigned long long ap[8] = {q0.x, q0.y, q1.x, q1.y, q2.x, q2.y, q3.x, q3.y};
            unsigned long long wp[4] = {r0.x, r0.y, r1.x, r1.y};
#pragma unroll
            for (int i = 0; i < 8; i++)
#pragma unroll
                for (int j = 0; j < 4; j++)
                    acc[i][j] = fma2(ap[i], wp[j], acc[i][j]);
        }
    }

    float4 b0 = *(const float4*)(bias + tn);
    float4 b1 = *(const float4*)(bias + tn + 4);
    float bb[8] = {b0.x, b0.y, b0.z, b0.w, b1.x, b1.y, b1.z, b1.w};
#pragma unroll
    for (int i = 0; i < 8; i++) {
        int row = rowBase + tm + i;
        if (row < NN) {
            float o[8];
#pragma unroll
            for (int j = 0; j < 4; j++) {
                float2 f = unpack2(acc[i][j]);
                o[2 * j]     = fmaxf(f.x + bb[2 * j], 0.f);
                o[2 * j + 1] = fmaxf(f.y + bb[2 * j + 1], 0.f);
            }
            *(float4*)(C + (size_t)row * HH + tn)     = make_float4(o[0], o[1], o[2], o[3]);
            *(float4*)(C + (size_t)row * HH + tn + 4) = make_float4(o[4], o[5], o[6], o[7]);
        }
    }
}

// ---------------------------------------------------------------------------
// Segment-sum scatter: one warp per input row, 4 floats per lane.
__global__ void pool_scatter(const float* __restrict__ h, const int* __restrict__ seg,
                             float* __restrict__ out, int n) {
    unsigned t = blockIdx.x * blockDim.x + threadIdx.x;
    unsigned i = t >> 5;
    if (i >= (unsigned)n) return;
    int lane = (int)(t & 31);
    int sg = seg[i];
    float4 v = *(const float4*)(h + (size_t)i * HH + lane * 4);
    float* o = out + (size_t)sg * HH + lane * 4;
    atomicAdd(o + 0, v.x);
    atomicAdd(o + 1, v.y);
    atomicAdd(o + 2, v.z);
    atomicAdd(o + 3, v.w);
}

// Head: per-graph MLP + log_softmax. One block per graph, 128 threads.
__global__ void head(const float* __restrict__ graph, const float* __restrict__ l1W,
                     const float* __restrict__ l1b, const float* __restrict__ l2W,
                     const float* __restrict__ l2b, float* __restrict__ out) {
    __shared__ float row[HH];
    __shared__ float h1[HH];
    __shared__ float red[HH];
    int g = blockIdx.x;
    int j = threadIdx.x;

    row[j] = graph[g * HH + j];
    __syncthreads();

    float acc = l1b[j];
#pragma unroll 8
    for (int k = 0; k < HH; k++) acc = fmaf(row[k], l1W[k * HH + j], acc);
    h1[j] = fmaxf(acc, 0.f);
    __syncthreads();

    float acc2 = l2b[j];
#pragma unroll 8
    for (int k = 0; k < HH; k++) acc2 = fmaf(h1[k], l2W[k * HH + j], acc2);

    red[j] = acc2;
    __syncthreads();
    for (int s = 64; s > 0; s >>= 1) {
        if (j < s) red[j] = fmaxf(red[j], red[j + s]);
        __syncthreads();
    }
    float m = red[0];
    __syncthreads();
    red[j] = expf(acc2 - m);
    __syncthreads();
    for (int s = 64; s > 0; s >>= 1) {
        if (j < s) red[j] += red[j + s];
        __syncthreads();
    }
    float lse = m + logf(red[0]);
    out[g * HH + j] = acc2 - lse;
}

// ---------------------------------------------------------------------------
extern "C" void kernel_launch(void* const* d_in, const int* in_sizes, int n_in,
                              void* d_out, int out_size) {
    const float* x   = (const float*)d_in[0];
    const int*   ei  = (const int*)  d_in[1];
    const int*   n2s = (const int*)  d_in[2];
    const int*   s2g = (const int*)  d_in[3];
    const float* W1a = (const float*)d_in[4];
    const float* b1a = (const float*)d_in[5];
    const float* W1b = (const float*)d_in[6];
    const float* b1b = (const float*)d_in[7];
    const float* cWa = (const float*)d_in[8];
    const float* cba = (const float*)d_in[9];
    const float* cWb = (const float*)d_in[10];
    const float* cbb = (const float*)d_in[11];
    const float* l1W = (const float*)d_in[12];
    const float* l1b = (const float*)d_in[13];
    const float* l2W = (const float*)d_in[14];
    const float* l2b = (const float*)d_in[15];
    float* out = (float*)d_out;

    const int* src = ei;
    const int* dst = ei + EE;

    float *ph, *ph2, *pag, *ppool;
    int *prp, *pbs, *pcur;
    cudaGetSymbolAddress((void**)&ph,    g_h);
    cudaGetSymbolAddress((void**)&ph2,   g_h2);
    cudaGetSymbolAddress((void**)&pag,   g_aggr);
    cudaGetSymbolAddress((void**)&ppool, g_pool);
    cudaGetSymbolAddress((void**)&prp,   g_rowptr);
    cudaGetSymbolAddress((void**)&pbs,   g_bsum);
    cudaGetSymbolAddress((void**)&pcur,  g_cur);

    float* psub = ppool;
    float* pgr  = ppool + SS * HH;

    const int TB = 256;
    const int gemmBlocks = (NN + 127) / 128;
    const int nScan = NN + 1;
    const int scanBlocks = (nScan + 1023) / 1024;  // 49
    const int initN = (SS + GG) * HH / 4;          // > NN+1

    // ---- init + CSR build ----
    init_zero<<<(initN + TB - 1) / TB, TB>>>(prp, (float4*)ppool);
    hist_dst<<<(EE + TB - 1) / TB, TB>>>(dst);
    scan1<<<scanBlocks, 1024>>>(prp, pbs, nScan);
    scan_finish<<<scanBlocks, 1024>>>(prp, pbs, pcur, nScan);
    fill_csr<<<(EE + TB - 1) / TB, TB>>>(src, dst);

    // ---- conv1: F_IN=2 ----
    aggr2_csr<<<(NN + TB - 1) / TB, TB>>>(x, pag);
    conv1_lin<<<(NN * HH + TB - 1) / TB, TB>>>(pag, W1a, b1a, ph2);
    gemm_relu<<<gemmBlocks, TB>>>(ph2, W1b, b1b, ph);

    // ---- convs 2..4: H=128 ----
    for (int i = 0; i < 3; i++) {
        aggr128_csr<<<(NN * 32 + TB - 1) / TB, TB>>>(ph, pag);
        gemm_relu<<<gemmBlocks, TB>>>(pag, cWa + i * HH * HH, cba + i * HH, ph2);
        gemm_relu<<<gemmBlocks, TB>>>(ph2, cWb + i * HH * HH, cbb + i * HH, ph);
    }

    // ---- nested pooling ----
    pool_scatter<<<(NN * 32 + TB - 1) / TB, TB>>>(ph, n2s, psub, NN);
    pool_scatter<<<(SS * 32 + TB - 1) / TB, TB>>>(psub, s2g, pgr, SS);

    // ---- head ----
    head<<<GG, HH>>>(pgr, l1W, l1b, l2W, l2b, out);
}

// round 4
// speedup vs baseline: 1.2539x; 1.2539x over previous
#include <cuda_runtime.h>
#include <math.h>

#define NN 50000
#define EE 800000
#define HH 128
#define SS 5000
#define GG 64

// Scratch (device globals: no allocation allowed)
__device__ float g_h   [NN*HH];
__device__ float g_aggr[NN*HH];
__device__ float g_pool[(SS+GG)*HH];
__device__ int   g_rowptr[NN+1];
__device__ int   g_cur[NN];
__device__ int   g_csr[EE];
__device__ int   g_bsum[64];

// ---------------------------------------------------------------------------
// packed f32x2 helpers
__device__ __forceinline__ unsigned long long pack2(float lo, float hi) {
    unsigned long long r;
    asm("mov.b64 %0, {%1, %2};" : "=l"(r) : "f"(lo), "f"(hi));
    return r;
}
__device__ __forceinline__ unsigned long long fma2(unsigned long long a,
                                                   unsigned long long b,
                                                   unsigned long long c) {
    unsigned long long d;
    asm("fma.rn.f32x2 %0, %1, %2, %3;" : "=l"(d) : "l"(a), "l"(b), "l"(c));
    return d;
}
__device__ __forceinline__ float2 unpack2(unsigned long long v) {
    float2 f;
    asm("mov.b64 {%0, %1}, %2;" : "=f"(f.x), "=f"(f.y) : "l"(v));
    return f;
}

// ---------------------------------------------------------------------------
// Combined zero-init: rowptr counters + pooling buffers
__global__ void init_zero(int* __restrict__ rowptr, float4* __restrict__ pool) {
    int i = blockIdx.x * blockDim.x + threadIdx.x;
    if (i < NN + 1) rowptr[i] = 0;
    if (i < (SS + GG) * HH / 4) pool[i] = make_float4(0.f, 0.f, 0.f, 0.f);
}

__global__ void hist_dst(const int* __restrict__ dst) {
    int e = blockIdx.x * blockDim.x + threadIdx.x;
    if (e < EE) atomicAdd(&g_rowptr[dst[e] + 1], 1);
}

// inclusive scan, 1024-wide blocks
__global__ void scan1(int* __restrict__ data, int* __restrict__ bsum, int n) {
    __shared__ int sh[1024];
    int gid = blockIdx.x * 1024 + threadIdx.x;
    int v = (gid < n) ? data[gid] : 0;
    sh[threadIdx.x] = v;
    __syncthreads();
    for (int off = 1; off < 1024; off <<= 1) {
        int t = (threadIdx.x >= off) ? sh[threadIdx.x - off] : 0;
        __syncthreads();
        sh[threadIdx.x] += t;
        __syncthreads();
    }
    if (gid < n) data[gid] = sh[threadIdx.x];
    if (threadIdx.x == 1023) bsum[blockIdx.x] = sh[1023];
}

// add exclusive block-prefix (computed in-kernel) + write cursor array
__global__ void scan_finish(int* __restrict__ data, const int* __restrict__ bsum,
                            int* __restrict__ cur, int n) {
    __shared__ int offs;
    if (threadIdx.x == 0) {
        int s = 0;
        for (int j = 0; j < blockIdx.x; j++) s += bsum[j];
        offs = s;
    }
    __syncthreads();
    int gid = blockIdx.x * 1024 + threadIdx.x;
    if (gid < n) {
        int v = data[gid] + offs;
        data[gid] = v;
        if (gid < NN) cur[gid] = v;
    }
}

__global__ void fill_csr(const int* __restrict__ src, const int* __restrict__ dst) {
    int e = blockIdx.x * blockDim.x + threadIdx.x;
    if (e >= EE) return;
    int d = dst[e];
    int pos = atomicAdd(&g_cur[d], 1);
    g_csr[pos] = src[e];
}

// ---------------------------------------------------------------------------
// conv1 aggregation (F_IN=2) via CSR gather: one thread per node
__global__ void aggr2_csr(const float* __restrict__ x, float* __restrict__ out) {
    int n = blockIdx.x * blockDim.x + threadIdx.x;
    if (n >= NN) return;
    float2 acc = *(const float2*)(x + 2 * n);
    int p = g_rowptr[n], e = g_rowptr[n + 1];
    for (; p < e; ++p) {
        int s = g_csr[p];
        float2 v = *(const float2*)(x + 2 * s);
        acc.x += v.x; acc.y += v.y;
    }
    *(float2*)(out + 2 * n) = acc;
}

// H=128 aggregation via CSR gather: one warp per node, 4 floats per lane.
__global__ void aggr128_csr(const float* __restrict__ h, float* __restrict__ out) {
    unsigned t = blockIdx.x * blockDim.x + threadIdx.x;
    unsigned n = t >> 5;
    if (n >= NN) return;
    int lane = (int)(t & 31);
    const float* hp = h + lane * 4;
    float4 acc = *(const float4*)(hp + (size_t)n * HH);
    int p = g_rowptr[n], e = g_rowptr[n + 1];
    for (; p + 3 < e; p += 4) {
        int s0 = g_csr[p], s1 = g_csr[p + 1], s2 = g_csr[p + 2], s3 = g_csr[p + 3];
        float4 v0 = *(const float4*)(hp + (size_t)s0 * HH);
        float4 v1 = *(const float4*)(hp + (size_t)s1 * HH);
        float4 v2 = *(const float4*)(hp + (size_t)s2 * HH);
        float4 v3 = *(const float4*)(hp + (size_t)s3 * HH);
        acc.x += (v0.x + v1.x) + (v2.x + v3.x);
        acc.y += (v0.y + v1.y) + (v2.y + v3.y);
        acc.z += (v0.z + v1.z) + (v2.z + v3.z);
        acc.w += (v0.w + v1.w) + (v2.w + v3.w);
    }
    for (; p < e; ++p) {
        int s = g_csr[p];
        float4 v = *(const float4*)(hp + (size_t)s * HH);
        acc.x += v.x; acc.y += v.y; acc.z += v.z; acc.w += v.w;
    }
    *(float4*)(out + (size_t)n * HH + lane * 4) = acc;
}

// ---------------------------------------------------------------------------
// Fused GIN MLP: C = relu(relu(A @ Wa + ba) @ Wb + bb)
// 256 threads, 128-row tile, thread = 8x8. Phase-1 uses the round-2 GEMM loop;
// the H1 tile stays in smem (k-major, XOR-swizzled) for phase 2.
// CONV1: phase-1 input is (N,2) @ Wa(2,128) computed directly.
//
// H1t layout: column c (=k for phase 2), rows r packed as float4 groups,
// float index = c*128 + (((r>>2) ^ ((c>>3)&31)) << 2) + (r&3).
// Writes (c varies across lanes) and reads (c fixed, r-broadcast) conflict-free.
template<bool CONV1>
__global__ void __launch_bounds__(256, 2)
gin_mlp(const float* __restrict__ A, const float* __restrict__ Wa,
        const float* __restrict__ ba, const float* __restrict__ Wb,
        const float* __restrict__ bb, float* __restrict__ C) {
    extern __shared__ float sm[];
    float* H1t = sm;                                   // 16384 floats (64KB)
    float (*As)[128] = (float(*)[128])(sm + 16384);    // [16][128]
    float (*Ws)[128] = (float(*)[128])(sm + 16384 + 2048);

    const int tid = threadIdx.x;
    const int tm = (tid >> 4) * 8;   // row offset in tile
    const int tn = (tid & 15) * 8;   // col offset
    const int rowBase = blockIdx.x * 128;

    const int lr = tid >> 1;          // A row to load
    const int lk = (tid & 1) * 8;     // k offset 0 or 8
    const int wr = tid >> 5;          // W row
    const int wc = (tid & 31) * 4;    // W col

    float o1[8][8];  // phase-1 output block (rows i, cols c)

    if (CONV1) {
        float4 wa0 = *(const float4*)(Wa + tn);
        float4 wa1 = *(const float4*)(Wa + tn + 4);
        float4 wb0 = *(const float4*)(Wa + HH + tn);
        float4 wb1 = *(const float4*)(Wa + HH + tn + 4);
        float4 b0  = *(const float4*)(ba + tn);
        float4 b1  = *(const float4*)(ba + tn + 4);
        float w0v[8] = {wa0.x, wa0.y, wa0.z, wa0.w, wa1.x, wa1.y, wa1.z, wa1.w};
        float w1v[8] = {wb0.x, wb0.y, wb0.z, wb0.w, wb1.x, wb1.y, wb1.z, wb1.w};
        float bv[8]  = {b0.x, b0.y, b0.z, b0.w, b1.x, b1.y, b1.z, b1.w};
#pragma unroll
        for (int i = 0; i < 8; i++) {
            int row = rowBase + tm + i;
            float a0 = 0.f, a1 = 0.f;
            if (row < NN) {
                float2 a = *(const float2*)(A + 2 * (size_t)row);
                a0 = a.x; a1 = a.y;
            }
#pragma unroll
            for (int c = 0; c < 8; c++)
                o1[i][c] = fmaxf(fmaf(a0, w0v[c], fmaf(a1, w1v[c], bv[c])), 0.f);
        }
    } else {
        const bool rowOK = (rowBase + lr) < NN;
        const float* Arow = A + (size_t)(rowBase + lr) * HH;

        unsigned long long acc[8][4];
#pragma unroll
        for (int i = 0; i < 8; i++)
#pragma unroll
            for (int j = 0; j < 4; j++) acc[i][j] = 0ull;

        for (int k0 = 0; k0 < HH; k0 += 16) {
            float4 a0 = make_float4(0.f, 0.f, 0.f, 0.f), a1 = a0;
            if (rowOK) {
                a0 = *(const float4*)(Arow + k0 + lk);
                a1 = *(const float4*)(Arow + k0 + lk + 4);
            }
            As[lk + 0][lr] = a0.x; As[lk + 1][lr] = a0.y;
            As[lk + 2][lr] = a0.z; As[lk + 3][lr] = a0.w;
            As[lk + 4][lr] = a1.x; As[lk + 5][lr] = a1.y;
            As[lk + 6][lr] = a1.z; As[lk + 7][lr] = a1.w;

            *(float4*)&Ws[wr][wc]     = *(const float4*)(Wa + (size_t)(k0 + wr) * HH + wc);
            *(float4*)&Ws[wr + 8][wc] = *(const float4*)(Wa + (size_t)(k0 + wr + 8) * HH + wc);
            __syncthreads();

#pragma unroll
            for (int kk = 0; kk < 16; kk++) {
                float4 av0 = *(const float4*)&As[kk][tm];
                float4 av1 = *(const float4*)&As[kk][tm + 4];
                ulonglong2 wv0 = *(const ulonglong2*)&Ws[kk][tn];
                ulonglong2 wv1 = *(const ulonglong2*)&Ws[kk][tn + 4];
                unsigned long long wp[4] = {wv0.x, wv0.y, wv1.x, wv1.y};
                float aa[8] = {av0.x, av0.y, av0.z, av0.w, av1.x, av1.y, av1.z, av1.w};
                unsigned long long ap[8];
#pragma unroll
                for (int i = 0; i < 8; i++) ap[i] = pack2(aa[i], aa[i]);
#pragma unroll
                for (int i = 0; i < 8; i++)
#pragma unroll
                    for (int j = 0; j < 4; j++)
                        acc[i][j] = fma2(ap[i], wp[j], acc[i][j]);
            }
            __syncthreads();
        }

        float4 b0 = *(const float4*)(ba + tn);
        float4 b1 = *(const float4*)(ba + tn + 4);
        float bv[8] = {b0.x, b0.y, b0.z, b0.w, b1.x, b1.y, b1.z, b1.w};
#pragma unroll
        for (int i = 0; i < 8; i++)
#pragma unroll
            for (int j = 0; j < 4; j++) {
                float2 f = unpack2(acc[i][j]);
                o1[i][2 * j]     = fmaxf(f.x + bv[2 * j], 0.f);
                o1[i][2 * j + 1] = fmaxf(f.y + bv[2 * j + 1], 0.f);
            }
    }

    // Store H1 tile to smem, k-major + swizzled. 16 conflict-free float4 STS.
#pragma unroll
    for (int c = 0; c < 8; c++) {
        int col = tn + c;
        int sw = (col >> 3) & 31;
        float* base = H1t + col * 128;
        *(float4*)&base[(((tm >> 2) ^ sw) << 2)] =
            make_float4(o1[0][c], o1[1][c], o1[2][c], o1[3][c]);
        *(float4*)&base[((((tm >> 2) + 1) ^ sw) << 2)] =
            make_float4(o1[4][c], o1[5][c], o1[6][c], o1[7][c]);
    }
    __syncthreads();

    // ---- phase 2: C = relu(H1 @ Wb + bb), A-operand from smem ----
    unsigned long long acc[8][4];
#pragma unroll
    for (int i = 0; i < 8; i++)
#pragma unroll
        for (int j = 0; j < 4; j++) acc[i][j] = 0ull;

    const int slot0 = tm >> 2;
    for (int k0 = 0; k0 < HH; k0 += 16) {
        *(float4*)&Ws[wr][wc]     = *(const float4*)(Wb + (size_t)(k0 + wr) * HH + wc);
        *(float4*)&Ws[wr + 8][wc] = *(const float4*)(Wb + (size_t)(k0 + wr + 8) * HH + wc);
        __syncthreads();

#pragma unroll
        for (int kk = 0; kk < 16; kk++) {
            int k = k0 + kk;
            int sw = (k >> 3) & 31;
            const float* hrow = H1t + k * 128;
            float4 av0 = *(const float4*)&hrow[((slot0 ^ sw) << 2)];
            float4 av1 = *(const float4*)&hrow[(((slot0 + 1) ^ sw) << 2)];
            ulonglong2 wv0 = *(const ulonglong2*)&Ws[kk][tn];
            ulonglong2 wv1 = *(const ulonglong2*)&Ws[kk][tn + 4];
            unsigned long long wp[4] = {wv0.x, wv0.y, wv1.x, wv1.y};
            float aa[8] = {av0.x, av0.y, av0.z, av0.w, av1.x, av1.y, av1.z, av1.w};
            unsigned long long ap[8];
#pragma unroll
            for (int i = 0; i < 8; i++) ap[i] = pack2(aa[i], aa[i]);
#pragma unroll
            for (int i = 0; i < 8; i++)
#pragma unroll
                for (int j = 0; j < 4; j++)
                    acc[i][j] = fma2(ap[i], wp[j], acc[i][j]);
        }
        __syncthreads();
    }

    float4 b0 = *(const float4*)(bb + tn);
    float4 b1 = *(const float4*)(bb + tn + 4);
    float bv[8] = {b0.x, b0.y, b0.z, b0.w, b1.x, b1.y, b1.z, b1.w};
#pragma unroll
    for (int i = 0; i < 8; i++) {
        int row = rowBase + tm + i;
        if (row < NN) {
            float o[8];
#pragma unroll
            for (int j = 0; j < 4; j++) {
                float2 f = unpack2(acc[i][j]);
                o[2 * j]     = fmaxf(f.x + bv[2 * j], 0.f);
                o[2 * j + 1] = fmaxf(f.y + bv[2 * j + 1], 0.f);
            }
            *(float4*)(C + (size_t)row * HH + tn)     = make_float4(o[0], o[1], o[2], o[3]);
            *(float4*)(C + (size_t)row * HH + tn + 4) = make_float4(o[4], o[5], o[6], o[7]);
        }
    }
}

// ---------------------------------------------------------------------------
// Segment-sum scatter: one warp per input row, 4 floats per lane.
__global__ void pool_scatter(const float* __restrict__ h, const int* __restrict__ seg,
                             float* __restrict__ out, int n) {
    unsigned t = blockIdx.x * blockDim.x + threadIdx.x;
    unsigned i = t >> 5;
    if (i >= (unsigned)n) return;
    int lane = (int)(t & 31);
    int sg = seg[i];
    float4 v = *(const float4*)(h + (size_t)i * HH + lane * 4);
    float* o = out + (size_t)sg * HH + lane * 4;
    atomicAdd(o + 0, v.x);
    atomicAdd(o + 1, v.y);
    atomicAdd(o + 2, v.z);
    atomicAdd(o + 3, v.w);
}

// Head: per-graph MLP + log_softmax. One block per graph, 128 threads.
__global__ void head(const float* __restrict__ graph, const float* __restrict__ l1W,
                     const float* __restrict__ l1b, const float* __restrict__ l2W,
                     const float* __restrict__ l2b, float* __restrict__ out) {
    __shared__ float row[HH];
    __shared__ float h1[HH];
    __shared__ float red[HH];
    int g = blockIdx.x;
    int j = threadIdx.x;

    row[j] = graph[g * HH + j];
    __syncthreads();

    float acc = l1b[j];
#pragma unroll 8
    for (int k = 0; k < HH; k++) acc = fmaf(row[k], l1W[k * HH + j], acc);
    h1[j] = fmaxf(acc, 0.f);
    __syncthreads();

    float acc2 = l2b[j];
#pragma unroll 8
    for (int k = 0; k < HH; k++) acc2 = fmaf(h1[k], l2W[k * HH + j], acc2);

    red[j] = acc2;
    __syncthreads();
    for (int s = 64; s > 0; s >>= 1) {
        if (j < s) red[j] = fmaxf(red[j], red[j + s]);
        __syncthreads();
    }
    float m = red[0];
    __syncthreads();
    red[j] = expf(acc2 - m);
    __syncthreads();
    for (int s = 64; s > 0; s >>= 1) {
        if (j < s) red[j] += red[j + s];
        __syncthreads();
    }
    float lse = m + logf(red[0]);
    out[g * HH + j] = acc2 - lse;
}

// ---------------------------------------------------------------------------
extern "C" void kernel_launch(void* const* d_in, const int* in_sizes, int n_in,
                              void* d_out, int out_size) {
    const float* x   = (const float*)d_in[0];
    const int*   ei  = (const int*)  d_in[1];
    const int*   n2s = (const int*)  d_in[2];
    const int*   s2g = (const int*)  d_in[3];
    const float* W1a = (const float*)d_in[4];
    const float* b1a = (const float*)d_in[5];
    const float* W1b = (const float*)d_in[6];
    const float* b1b = (const float*)d_in[7];
    const float* cWa = (const float*)d_in[8];
    const float* cba = (const float*)d_in[9];
    const float* cWb = (const float*)d_in[10];
    const float* cbb = (const float*)d_in[11];
    const float* l1W = (const float*)d_in[12];
    const float* l1b = (const float*)d_in[13];
    const float* l2W = (const float*)d_in[14];
    const float* l2b = (const float*)d_in[15];
    float* out = (float*)d_out;

    const int* src = ei;
    const int* dst = ei + EE;

    float *ph, *pag, *ppool;
    int *prp, *pbs, *pcur;
    cudaGetSymbolAddress((void**)&ph,    g_h);
    cudaGetSymbolAddress((void**)&pag,   g_aggr);
    cudaGetSymbolAddress((void**)&ppool, g_pool);
    cudaGetSymbolAddress((void**)&prp,   g_rowptr);
    cudaGetSymbolAddress((void**)&pbs,   g_bsum);
    cudaGetSymbolAddress((void**)&pcur,  g_cur);

    float* psub = ppool;
    float* pgr  = ppool + SS * HH;

    const int TB = 256;
    const int gemmBlocks = (NN + 127) / 128;
    const int nScan = NN + 1;
    const int scanBlocks = (nScan + 1023) / 1024;
    const int initN = (SS + GG) * HH / 4;
    const int SMEM = (16384 + 2048 + 2048) * 4;  // 80KB

    cudaFuncSetAttribute(gin_mlp<true>,  cudaFuncAttributeMaxDynamicSharedMemorySize, SMEM);
    cudaFuncSetAttribute(gin_mlp<false>, cudaFuncAttributeMaxDynamicSharedMemorySize, SMEM);

    // ---- init + CSR build ----
    init_zero<<<(initN + TB - 1) / TB, TB>>>(prp, (float4*)ppool);
    hist_dst<<<(EE + TB - 1) / TB, TB>>>(dst);
    scan1<<<scanBlocks, 1024>>>(prp, pbs, nScan);
    scan_finish<<<scanBlocks, 1024>>>(prp, pbs, pcur, nScan);
    fill_csr<<<(EE + TB - 1) / TB, TB>>>(src, dst);

    // ---- conv1 ----
    aggr2_csr<<<(NN + TB - 1) / TB, TB>>>(x, pag);
    gin_mlp<true><<<gemmBlocks, TB, SMEM>>>(pag, W1a, b1a, W1b, b1b, ph);

    // ---- convs 2..4 ----
    for (int i = 0; i < 3; i++) {
        aggr128_csr<<<(NN * 32 + TB - 1) / TB, TB>>>(ph, pag);
        gin_mlp<false><<<gemmBlocks, TB, SMEM>>>(pag, cWa + i * HH * HH, cba + i * HH,
                                                 cWb + i * HH * HH, cbb + i * HH, ph);
    }

    // ---- nested pooling ----
    pool_scatter<<<(NN * 32 + TB - 1) / TB, TB>>>(ph, n2s, psub, NN);
    pool_scatter<<<(SS * 32 + TB - 1) / TB, TB>>>(psub, s2g, pgr, SS);

    // ---- head ----
    head<<<GG, HH>>>(pgr, l1W, l1b, l2W, l2b, out);
}